// round 4
// baseline (speedup 1.0000x reference)
#include <cuda_runtime.h>
#include <cuda_bf16.h>
#include <math_constants.h>

#define T_SEQ 4096
#define H_DIM 2048
#define I_DIM 8192

// ---------------- scratch (device globals; no runtime allocation) ----------------
__device__ float g_x  [T_SEQ * H_DIM];   // LN output (x, then x2)
__device__ float g_kx [T_SEQ * H_DIM];   // key mix / ffn key mix
__device__ float g_vx [T_SEQ * H_DIM];   // value mix
__device__ float g_rx [T_SEQ * H_DIM];   // receptance mix / ffn receptance mix
__device__ float g_k  [T_SEQ * H_DIM];   // k
__device__ float g_v  [T_SEQ * H_DIM];   // v, later kv = kk@Wv_ff
__device__ float g_r  [T_SEQ * H_DIM];   // sigmoid(r), later rr
__device__ float g_wkv[T_SEQ * H_DIM];   // r * wkv
__device__ float g_kk [(size_t)T_SEQ * I_DIM]; // relu(xk@Wk_ff)^2

// ---------------- LayerNorm: one block per row ----------------
__global__ __launch_bounds__(256) void ln_kernel(const float* __restrict__ in,
                                                 const float* __restrict__ sc,
                                                 const float* __restrict__ bi,
                                                 float* __restrict__ out) {
    __shared__ float red0[8], red1[8];
    const int t = blockIdx.x;
    const float* row = in + (size_t)t * H_DIM;
    float v[8];
    float s = 0.f, ss = 0.f;
#pragma unroll
    for (int i = 0; i < 8; i++) {
        v[i] = row[threadIdx.x + i * 256];
        s += v[i];
        ss += v[i] * v[i];
    }
#pragma unroll
    for (int o = 16; o; o >>= 1) {
        s  += __shfl_xor_sync(0xffffffffu, s, o);
        ss += __shfl_xor_sync(0xffffffffu, ss, o);
    }
    const int w = threadIdx.x >> 5, l = threadIdx.x & 31;
    if (l == 0) { red0[w] = s; red1[w] = ss; }
    __syncthreads();
    if (threadIdx.x < 32) {
        s  = (l < 8) ? red0[l] : 0.f;
        ss = (l < 8) ? red1[l] : 0.f;
#pragma unroll
        for (int o = 4; o; o >>= 1) {
            s  += __shfl_xor_sync(0xffffffffu, s, o);
            ss += __shfl_xor_sync(0xffffffffu, ss, o);
        }
        if (l == 0) { red0[0] = s; red1[0] = ss; }
    }
    __syncthreads();
    const float mean = red0[0] * (1.f / H_DIM);
    const float var  = red1[0] * (1.f / H_DIM) - mean * mean;
    const float inv  = rsqrtf(var + 1e-5f);
    float* orow = out + (size_t)t * H_DIM;
#pragma unroll
    for (int i = 0; i < 8; i++) {
        const int h = threadIdx.x + i * 256;
        orow[h] = (v[i] - mean) * inv * sc[h] + bi[h];
    }
}

// ---------------- token-shift mixes ----------------
__global__ __launch_bounds__(256) void mix3_kernel(const float* __restrict__ x,
                                                   const float* __restrict__ tmk,
                                                   const float* __restrict__ tmv,
                                                   const float* __restrict__ tmr,
                                                   float* __restrict__ kx,
                                                   float* __restrict__ vx,
                                                   float* __restrict__ rx) {
    const int idx = blockIdx.x * 256 + threadIdx.x;
    const int h = idx & (H_DIM - 1);
    const float xv = x[idx];
    const float cx = (idx >= H_DIM) ? x[idx - H_DIM] : 0.f;
    const float a = tmk[h], b = tmv[h], c = tmr[h];
    kx[idx] = xv * a + cx * (1.f - a);
    vx[idx] = xv * b + cx * (1.f - b);
    rx[idx] = xv * c + cx * (1.f - c);
}

__global__ __launch_bounds__(256) void mix2_kernel(const float* __restrict__ x,
                                                   const float* __restrict__ tmk,
                                                   const float* __restrict__ tmr,
                                                   float* __restrict__ kx,
                                                   float* __restrict__ rx) {
    const int idx = blockIdx.x * 256 + threadIdx.x;
    const int h = idx & (H_DIM - 1);
    const float xv = x[idx];
    const float cx = (idx >= H_DIM) ? x[idx - H_DIM] : 0.f;
    const float a = tmk[h], c = tmr[h];
    kx[idx] = xv * a + cx * (1.f - a);
    rx[idx] = xv * c + cx * (1.f - c);
}

// ---------------- WKV serial scan: one thread per channel; writes r*wkv ----------------
__global__ __launch_bounds__(256) void wkv_kernel(const float* __restrict__ k,
                                                  const float* __restrict__ v,
                                                  const float* __restrict__ r,
                                                  const float* __restrict__ time_first,
                                                  const float* __restrict__ time_decay,
                                                  float* __restrict__ out) {
    const int h = blockIdx.x * 256 + threadIdx.x;  // 0..H-1
    const float u = time_first[h];
    const float w = -__expf(time_decay[h]);  // decay (negative)
    float aa = 0.f, bb = 0.f, pp = -CUDART_INF_F;
    for (int t = 0; t < T_SEQ; t++) {
        const size_t idx = (size_t)t * H_DIM + h;
        const float kk = k[idx];
        const float vv = v[idx];
        const float ww = u + kk;
        const float p  = fmaxf(pp, ww);
        const float e1 = __expf(pp - p);
        const float e2 = __expf(ww - p);
        const float o  = (e1 * aa + e2 * vv) / (e1 * bb + e2);
        out[idx] = r[idx] * o;
        const float ww2 = w + pp;
        const float p2  = fmaxf(ww2, kk);
        const float e1b = __expf(ww2 - p2);
        const float e2b = __expf(kk - p2);
        aa = e1b * aa + e2b * vv;
        bb = e1b * bb + e2b;
        pp = p2;
    }
}

// ---------------- final gated residual: out += rr * kv ----------------
__global__ __launch_bounds__(256) void gate_add_kernel(float* __restrict__ out,
                                                       const float* __restrict__ rr,
                                                       const float* __restrict__ kv) {
    const int idx = blockIdx.x * 256 + threadIdx.x;
    out[idx] += rr[idx] * kv[idx];
}

// ---------------- SGEMM: C[M,N] = A[M,K] @ B[K,N], row-major, fp32 ----------------
// 128x128 tile, BK=8, 256 threads, 8x8 per thread.
// EPI: 0 = none, 1 = sigmoid, 2 = relu^2, 3 = += res
template <int EPI>
__global__ __launch_bounds__(256) void sgemm_kernel(const float* __restrict__ A,
                                                    const float* __restrict__ B,
                                                    float* __restrict__ C,
                                                    const float* __restrict__ res,
                                                    int M, int N, int K) {
    __shared__ float As[8][128];
    __shared__ float Bs[8][128];

    const int tid = threadIdx.x;
    const int bm = blockIdx.y * 128;
    const int bn = blockIdx.x * 128;
    const int tm = (tid >> 4) * 8;   // 0..120
    const int tn = (tid & 15) * 8;   // 0..120

    const int arow = tid >> 1;          // 0..127
    const int acg  = (tid & 1) * 4;     // 0 or 4
    const int brow = tid >> 5;          // 0..7
    const int bcol = (tid & 31) * 4;    // 0..124

    const float* Aptr = A + (size_t)(bm + arow) * K + acg;
    const float* Bptr = B + (size_t)brow * N + bn + bcol;

    float acc[8][8];
#pragma unroll
    for (int i = 0; i < 8; i++)
#pragma unroll
        for (int j = 0; j < 8; j++) acc[i][j] = 0.f;

    for (int kt = 0; kt < K; kt += 8) {
        const float4 a4 = *reinterpret_cast<const float4*>(Aptr + kt);
        const float4 b4 = *reinterpret_cast<const float4*>(Bptr + (size_t)kt * N);
        As[acg + 0][arow] = a4.x;
        As[acg + 1][arow] = a4.y;
        As[acg + 2][arow] = a4.z;
        As[acg + 3][arow] = a4.w;
        *reinterpret_cast<float4*>(&Bs[brow][bcol]) = b4;
        __syncthreads();
#pragma unroll
        for (int kk = 0; kk < 8; kk++) {
            float ar[8], br[8];
            *reinterpret_cast<float4*>(&ar[0]) = *reinterpret_cast<const float4*>(&As[kk][tm]);
            *reinterpret_cast<float4*>(&ar[4]) = *reinterpret_cast<const float4*>(&As[kk][tm + 4]);
            *reinterpret_cast<float4*>(&br[0]) = *reinterpret_cast<const float4*>(&Bs[kk][tn]);
            *reinterpret_cast<float4*>(&br[4]) = *reinterpret_cast<const float4*>(&Bs[kk][tn + 4]);
#pragma unroll
            for (int i = 0; i < 8; i++)
#pragma unroll
                for (int j = 0; j < 8; j++) acc[i][j] = fmaf(ar[i], br[j], acc[i][j]);
        }
        __syncthreads();
    }

#pragma unroll
    for (int i = 0; i < 8; i++) {
        const size_t base = (size_t)(bm + tm + i) * N + bn + tn;
        float vals[8];
#pragma unroll
        for (int j = 0; j < 8; j++) {
            float xv = acc[i][j];
            if (EPI == 1) {
                xv = 1.f / (1.f + __expf(-xv));
            } else if (EPI == 2) {
                xv = fmaxf(xv, 0.f);
                xv = xv * xv;
            } else if (EPI == 3) {
                xv += res[base + j];
            }
            vals[j] = xv;
        }
        *reinterpret_cast<float4*>(&C[base])     = make_float4(vals[0], vals[1], vals[2], vals[3]);
        *reinterpret_cast<float4*>(&C[base + 4]) = make_float4(vals[4], vals[5], vals[6], vals[7]);
    }
}

// ---------------- launch ----------------
extern "C" void kernel_launch(void* const* d_in, const int* in_sizes, int n_in,
                              void* d_out, int out_size) {
    const float* hidden     = (const float*)d_in[0];
    const float* ln1_scale  = (const float*)d_in[1];
    const float* ln1_bias   = (const float*)d_in[2];
    const float* ln2_scale  = (const float*)d_in[3];
    const float* ln2_bias   = (const float*)d_in[4];
    const float* time_decay = (const float*)d_in[5];
    const float* time_first = (const float*)d_in[6];
    const float* tm_k       = (const float*)d_in[7];
    const float* tm_v       = (const float*)d_in[8];
    const float* tm_r       = (const float*)d_in[9];
    const float* Wk         = (const float*)d_in[10];
    const float* Wv         = (const float*)d_in[11];
    const float* Wr         = (const float*)d_in[12];
    const float* Wo         = (const float*)d_in[13];
    const float* ffn_tm_k   = (const float*)d_in[14];
    const float* ffn_tm_r   = (const float*)d_in[15];
    const float* Wk_ff      = (const float*)d_in[16];
    const float* Wv_ff      = (const float*)d_in[17];
    const float* Wr_ff      = (const float*)d_in[18];
    float* out = (float*)d_out;

    float *x, *kx, *vx, *rx, *k, *v, *r, *wkv, *kkb;
    cudaGetSymbolAddress((void**)&x,   g_x);
    cudaGetSymbolAddress((void**)&kx,  g_kx);
    cudaGetSymbolAddress((void**)&vx,  g_vx);
    cudaGetSymbolAddress((void**)&rx,  g_rx);
    cudaGetSymbolAddress((void**)&k,   g_k);
    cudaGetSymbolAddress((void**)&v,   g_v);
    cudaGetSymbolAddress((void**)&r,   g_r);
    cudaGetSymbolAddress((void**)&wkv, g_wkv);
    cudaGetSymbolAddress((void**)&kkb, g_kk);

    const int elemBlocks = (T_SEQ * H_DIM) / 256;
    const dim3 gH(H_DIM / 128, T_SEQ / 128);   // N = 2048 output
    const dim3 gI(I_DIM / 128, T_SEQ / 128);   // N = 8192 output

    // ---- time-mix ----
    ln_kernel<<<T_SEQ, 256>>>(hidden, ln1_scale, ln1_bias, x);
    mix3_kernel<<<elemBlocks, 256>>>(x, tm_k, tm_v, tm_r, kx, vx, rx);
    sgemm_kernel<1><<<gH, 256>>>(rx, Wr, r, nullptr, T_SEQ, H_DIM, H_DIM);   // r = sigmoid(rx@Wr)
    sgemm_kernel<0><<<gH, 256>>>(kx, Wk, k, nullptr, T_SEQ, H_DIM, H_DIM);
    sgemm_kernel<0><<<gH, 256>>>(vx, Wv, v, nullptr, T_SEQ, H_DIM, H_DIM);
    wkv_kernel<<<H_DIM / 256, 256>>>(k, v, r, time_first, time_decay, wkv);  // wkv = r * wkv
    sgemm_kernel<3><<<gH, 256>>>(wkv, Wo, out, hidden, T_SEQ, H_DIM, H_DIM); // out = hidden + (r*wkv)@Wo

    // ---- channel-mix ----
    ln_kernel<<<T_SEQ, 256>>>(out, ln2_scale, ln2_bias, x);
    mix2_kernel<<<elemBlocks, 256>>>(x, ffn_tm_k, ffn_tm_r, kx, rx);
    sgemm_kernel<1><<<gH, 256>>>(rx, Wr_ff, r, nullptr, T_SEQ, H_DIM, H_DIM);   // rr
    sgemm_kernel<2><<<gI, 256>>>(kx, Wk_ff, kkb, nullptr, T_SEQ, I_DIM, H_DIM); // kk = relu(.)^2
    sgemm_kernel<0><<<gH, 256>>>(kkb, Wv_ff, v, nullptr, T_SEQ, H_DIM, I_DIM);  // kv
    gate_add_kernel<<<elemBlocks, 256>>>(out, r, v);                            // out += rr*kv
}

// round 8
// speedup vs baseline: 1.8687x; 1.8687x over previous
#include <cuda_runtime.h>
#include <cuda_bf16.h>
#include <math_constants.h>
#include <cstdint>

#define T_SEQ 4096
#define H_DIM 2048
#define I_DIM 8192

// ---------------- scratch (device globals; no runtime allocation) ----------------
__device__ float g_x  [T_SEQ * H_DIM];
__device__ float g_kx [T_SEQ * H_DIM];
__device__ float g_vx [T_SEQ * H_DIM];
__device__ float g_rx [T_SEQ * H_DIM];
__device__ float g_k  [T_SEQ * H_DIM];
__device__ float g_v  [T_SEQ * H_DIM];
__device__ float g_r  [T_SEQ * H_DIM];
__device__ float g_wkv[T_SEQ * H_DIM];
__device__ float g_kk [(size_t)T_SEQ * I_DIM];
// bf16 split buffers (A: activations, B: transposed weights, K-major)
__device__ __nv_bfloat16 g_Ah[(size_t)T_SEQ * I_DIM];
__device__ __nv_bfloat16 g_Al[(size_t)T_SEQ * I_DIM];
__device__ __nv_bfloat16 g_Bh[(size_t)H_DIM * I_DIM];
__device__ __nv_bfloat16 g_Bl[(size_t)H_DIM * I_DIM];

// ---------------- helpers ----------------
__device__ __forceinline__ uint32_t smem_u32(const void* p) {
    uint32_t a;
    asm("{ .reg .u64 t; cvta.to.shared.u64 t, %1; cvt.u32.u64 %0, t; }" : "=r"(a) : "l"(p));
    return a;
}
#define SWZ128(o) ((o) ^ (((o) >> 3) & 0x70))

__device__ __forceinline__ void cp_async16(uint32_t dst, const void* src) {
    asm volatile("cp.async.cg.shared.global [%0], [%1], 16;" :: "r"(dst), "l"(src));
}
#define CP_COMMIT() asm volatile("cp.async.commit_group;" ::: "memory")

__device__ __forceinline__ void ldm_x4(uint32_t* r, uint32_t addr) {
    asm volatile("ldmatrix.sync.aligned.m8n8.x4.shared.b16 {%0,%1,%2,%3}, [%4];"
                 : "=r"(r[0]), "=r"(r[1]), "=r"(r[2]), "=r"(r[3]) : "r"(addr));
}
__device__ __forceinline__ void mma16816(float* c, const uint32_t* a, const uint32_t* b) {
    asm volatile(
        "mma.sync.aligned.m16n8k16.row.col.f32.bf16.bf16.f32 "
        "{%0,%1,%2,%3}, {%4,%5,%6,%7}, {%8,%9}, {%0,%1,%2,%3};"
        : "+f"(c[0]), "+f"(c[1]), "+f"(c[2]), "+f"(c[3])
        : "r"(a[0]), "r"(a[1]), "r"(a[2]), "r"(a[3]), "r"(b[0]), "r"(b[1]));
}

// ---------------- mma.sync GEMM: C[M,N] = A[M,K] @ B[N,K]^T  (3-term bf16 split) -------
// BM=128, BN=128, BK=64, 256 threads; cp.async 2-stage double buffer; SW128 smem.
// EPI: 0=none 1=sigmoid 2=relu^2 3=+=res
template <int EPI>
__global__ __launch_bounds__(256) void mma_gemm(const __nv_bfloat16* __restrict__ Ah,
                                                const __nv_bfloat16* __restrict__ Al,
                                                const __nv_bfloat16* __restrict__ Bh,
                                                const __nv_bfloat16* __restrict__ Bl,
                                                float* __restrict__ C,
                                                const float* __restrict__ res,
                                                int M, int N, int K) {
    extern __shared__ char dsm[];
    char* smem = (char*)(((uintptr_t)dsm + 1023u) & ~(uintptr_t)1023u);
    const uint32_t sbase = smem_u32(smem);

    const int tid = threadIdx.x;
    const int wid = tid >> 5, lane = tid & 31;
    const int warp_m = wid & 3;        // 4 warps along M (32 rows each)
    const int warp_n = wid >> 2;       // 2 warps along N (64 cols each)
    const int bm = blockIdx.y * 128, bn = blockIdx.x * 128;

    const int KC = K >> 6;             // 64-wide K chunks per region
    const int NC = 3 * KC;             // 3 split terms: AhBh, AlBh, AhBl

    const int lrow = tid >> 3;         // 0..31 (cp.async row)
    const int lseg = tid & 7;          // 0..7  (16B segment)

    // ldmatrix per-lane coordinates
    const int a_row = (lane & 15);             // A: row within 16-row tile
    const int a_kb  = (lane >> 4) * 16;        // A: k-half byte offset
    const int b_row = (lane & 7) + ((lane >> 4) << 3);  // B: n within 16-n pair
    const int b_kb  = ((lane >> 3) & 1) * 16;  // B: k-half byte offset

    float acc[2][8][4];
#pragma unroll
    for (int i = 0; i < 2; i++)
#pragma unroll
        for (int j = 0; j < 8; j++)
#pragma unroll
            for (int q = 0; q < 4; q++) acc[i][j][q] = 0.f;

    // issue cp.async loads for chunk c into buffer p
    auto issue = [&](int c, int p) {
        const int region = c / KC;
        const int k0 = (c - region * KC) << 6;
        const __nv_bfloat16* Asrc = (region == 1) ? Al : Ah;
        const __nv_bfloat16* Bsrc = (region == 2) ? Bl : Bh;
        const uint32_t abuf = sbase + p * 32768;
        const uint32_t bbuf = abuf + 16384;
#pragma unroll
        for (int i = 0; i < 4; i++) {
            const int row = i * 32 + lrow;
            const uint32_t off = SWZ128((uint32_t)(row * 128 + lseg * 16));
            cp_async16(abuf + off, Asrc + (size_t)(bm + row) * K + k0 + lseg * 8);
            cp_async16(bbuf + off, Bsrc + (size_t)(bn + row) * K + k0 + lseg * 8);
        }
        CP_COMMIT();
    };

    issue(0, 0);

    for (int c = 0; c < NC; c++) {
        const int p = c & 1;
        if (c + 1 < NC) {
            issue(c + 1, p ^ 1);
            asm volatile("cp.async.wait_group 1;" ::: "memory");
        } else {
            asm volatile("cp.async.wait_group 0;" ::: "memory");
        }
        __syncthreads();

        const uint32_t abuf = sbase + p * 32768;
        const uint32_t bbuf = abuf + 16384;
#pragma unroll
        for (int ks = 0; ks < 4; ks++) {
            uint32_t afr[2][4];
#pragma unroll
            for (int mt = 0; mt < 2; mt++) {
                const uint32_t off = (uint32_t)((warp_m * 32 + mt * 16 + a_row) * 128 + ks * 32 + a_kb);
                ldm_x4(afr[mt], abuf + SWZ128(off));
            }
            uint32_t bfr[8][2];
#pragma unroll
            for (int np = 0; np < 4; np++) {
                uint32_t r[4];
                const uint32_t off = (uint32_t)((warp_n * 64 + np * 16 + b_row) * 128 + ks * 32 + b_kb);
                ldm_x4(r, bbuf + SWZ128(off));
                bfr[2 * np][0] = r[0];  bfr[2 * np][1] = r[1];
                bfr[2 * np + 1][0] = r[2];  bfr[2 * np + 1][1] = r[3];
            }
#pragma unroll
            for (int mt = 0; mt < 2; mt++)
#pragma unroll
                for (int nt = 0; nt < 8; nt++)
                    mma16816(acc[mt][nt], afr[mt], bfr[nt]);
        }
        __syncthreads();
    }

    // ---- epilogue ----
    const int trow = lane >> 2;
    const int tcol = (lane & 3) * 2;
#pragma unroll
    for (int mt = 0; mt < 2; mt++) {
#pragma unroll
        for (int nt = 0; nt < 8; nt++) {
            const int row0 = bm + warp_m * 32 + mt * 16 + trow;
            const int col  = bn + warp_n * 64 + nt * 8 + tcol;
#pragma unroll
            for (int h = 0; h < 2; h++) {
                const int row = row0 + h * 8;
                float v0 = acc[mt][nt][2 * h + 0];
                float v1 = acc[mt][nt][2 * h + 1];
                const size_t base = (size_t)row * N + col;
                if (EPI == 1) {
                    v0 = 1.f / (1.f + __expf(-v0));
                    v1 = 1.f / (1.f + __expf(-v1));
                } else if (EPI == 2) {
                    v0 = fmaxf(v0, 0.f); v0 *= v0;
                    v1 = fmaxf(v1, 0.f); v1 *= v1;
                } else if (EPI == 3) {
                    const float2 rv = *reinterpret_cast<const float2*>(&res[base]);
                    v0 += rv.x; v1 += rv.y;
                }
                *reinterpret_cast<float2*>(&C[base]) = make_float2(v0, v1);
            }
        }
    }
}

// ---------------- conversions ----------------
__global__ __launch_bounds__(256) void convert_act(const float* __restrict__ X,
                                                   __nv_bfloat16* __restrict__ Hh,
                                                   __nv_bfloat16* __restrict__ Hl) {
    const int i = blockIdx.x * 256 + threadIdx.x;
    const float v = X[i];
    const __nv_bfloat16 h = __float2bfloat16(v);
    Hh[i] = h;
    Hl[i] = __float2bfloat16(v - __bfloat162float(h));
}

// W [K,N] fp32 -> WT_hi/WT_lo [N,K] bf16 (transpose + split)
__global__ __launch_bounds__(256) void convert_wt(const float* __restrict__ W,
                                                  __nv_bfloat16* __restrict__ Th,
                                                  __nv_bfloat16* __restrict__ Tl,
                                                  int K, int N) {
    __shared__ float tile[32][33];
    const int tx = threadIdx.x & 31, ty = threadIdx.x >> 5;   // 32 x 8
    const int k0 = blockIdx.y * 32, n0 = blockIdx.x * 32;
#pragma unroll
    for (int j = 0; j < 4; j++)
        tile[ty + j * 8][tx] = W[(size_t)(k0 + ty + j * 8) * N + n0 + tx];
    __syncthreads();
#pragma unroll
    for (int j = 0; j < 4; j++) {
        const float v = tile[tx][ty + j * 8];
        const __nv_bfloat16 h = __float2bfloat16(v);
        const size_t o = (size_t)(n0 + ty + j * 8) * K + k0 + tx;
        Th[o] = h;
        Tl[o] = __float2bfloat16(v - __bfloat162float(h));
    }
}

// ---------------- LayerNorm ----------------
__global__ __launch_bounds__(256) void ln_kernel(const float* __restrict__ in,
                                                 const float* __restrict__ sc,
                                                 const float* __restrict__ bi,
                                                 float* __restrict__ out) {
    __shared__ float red0[8], red1[8];
    const int t = blockIdx.x;
    const float* row = in + (size_t)t * H_DIM;
    float v[8];
    float s = 0.f, ss = 0.f;
#pragma unroll
    for (int i = 0; i < 8; i++) {
        v[i] = row[threadIdx.x + i * 256];
        s += v[i]; ss += v[i] * v[i];
    }
#pragma unroll
    for (int o = 16; o; o >>= 1) {
        s  += __shfl_xor_sync(0xffffffffu, s, o);
        ss += __shfl_xor_sync(0xffffffffu, ss, o);
    }
    const int w = threadIdx.x >> 5, l = threadIdx.x & 31;
    if (l == 0) { red0[w] = s; red1[w] = ss; }
    __syncthreads();
    if (threadIdx.x < 32) {
        s  = (l < 8) ? red0[l] : 0.f;
        ss = (l < 8) ? red1[l] : 0.f;
#pragma unroll
        for (int o = 4; o; o >>= 1) {
            s  += __shfl_xor_sync(0xffffffffu, s, o);
            ss += __shfl_xor_sync(0xffffffffu, ss, o);
        }
        if (l == 0) { red0[0] = s; red1[0] = ss; }
    }
    __syncthreads();
    const float mean = red0[0] * (1.f / H_DIM);
    const float var  = red1[0] * (1.f / H_DIM) - mean * mean;
    const float inv  = rsqrtf(var + 1e-5f);
    float* orow = out + (size_t)t * H_DIM;
#pragma unroll
    for (int i = 0; i < 8; i++) {
        const int h = threadIdx.x + i * 256;
        orow[h] = (v[i] - mean) * inv * sc[h] + bi[h];
    }
}

// ---------------- token-shift mixes ----------------
__global__ __launch_bounds__(256) void mix3_kernel(const float* __restrict__ x,
                                                   const float* __restrict__ tmk,
                                                   const float* __restrict__ tmv,
                                                   const float* __restrict__ tmr,
                                                   float* __restrict__ kx,
                                                   float* __restrict__ vx,
                                                   float* __restrict__ rx) {
    const int idx = blockIdx.x * 256 + threadIdx.x;
    const int h = idx & (H_DIM - 1);
    const float xv = x[idx];
    const float cx = (idx >= H_DIM) ? x[idx - H_DIM] : 0.f;
    const float a = tmk[h], b = tmv[h], c = tmr[h];
    kx[idx] = xv * a + cx * (1.f - a);
    vx[idx] = xv * b + cx * (1.f - b);
    rx[idx] = xv * c + cx * (1.f - c);
}

__global__ __launch_bounds__(256) void mix2_kernel(const float* __restrict__ x,
                                                   const float* __restrict__ tmk,
                                                   const float* __restrict__ tmr,
                                                   float* __restrict__ kx,
                                                   float* __restrict__ rx) {
    const int idx = blockIdx.x * 256 + threadIdx.x;
    const int h = idx & (H_DIM - 1);
    const float xv = x[idx];
    const float cx = (idx >= H_DIM) ? x[idx - H_DIM] : 0.f;
    const float a = tmk[h], c = tmr[h];
    kx[idx] = xv * a + cx * (1.f - a);
    rx[idx] = xv * c + cx * (1.f - c);
}

// ---------------- WKV serial scan ----------------
__global__ __launch_bounds__(256) void wkv_kernel(const float* __restrict__ k,
                                                  const float* __restrict__ v,
                                                  const float* __restrict__ r,
                                                  const float* __restrict__ time_first,
                                                  const float* __restrict__ time_decay,
                                                  float* __restrict__ out) {
    const int h = blockIdx.x * 256 + threadIdx.x;
    const float u = time_first[h];
    const float w = -__expf(time_decay[h]);
    float aa = 0.f, bb = 0.f, pp = -CUDART_INF_F;
    for (int t = 0; t < T_SEQ; t++) {
        const size_t idx = (size_t)t * H_DIM + h;
        const float kk = k[idx];
        const float vv = v[idx];
        const float ww = u + kk;
        const float p  = fmaxf(pp, ww);
        const float e1 = __expf(pp - p);
        const float e2 = __expf(ww - p);
        const float o  = (e1 * aa + e2 * vv) / (e1 * bb + e2);
        out[idx] = r[idx] * o;
        const float ww2 = w + pp;
        const float p2  = fmaxf(ww2, kk);
        const float e1b = __expf(ww2 - p2);
        const float e2b = __expf(kk - p2);
        aa = e1b * aa + e2b * vv;
        bb = e1b * bb + e2b;
        pp = p2;
    }
}

__global__ __launch_bounds__(256) void gate_add_kernel(float* __restrict__ out,
                                                       const float* __restrict__ rr,
                                                       const float* __restrict__ kv) {
    const int idx = blockIdx.x * 256 + threadIdx.x;
    out[idx] += rr[idx] * kv[idx];
}

// ---------------- launch ----------------
extern "C" void kernel_launch(void* const* d_in, const int* in_sizes, int n_in,
                              void* d_out, int out_size) {
    const float* hidden     = (const float*)d_in[0];
    const float* ln1_scale  = (const float*)d_in[1];
    const float* ln1_bias   = (const float*)d_in[2];
    const float* ln2_scale  = (const float*)d_in[3];
    const float* ln2_bias   = (const float*)d_in[4];
    const float* time_decay = (const float*)d_in[5];
    const float* time_first = (const float*)d_in[6];
    const float* tm_k       = (const float*)d_in[7];
    const float* tm_v       = (const float*)d_in[8];
    const float* tm_r       = (const float*)d_in[9];
    const float* Wk         = (const float*)d_in[10];
    const float* Wv         = (const float*)d_in[11];
    const float* Wr         = (const float*)d_in[12];
    const float* Wo         = (const float*)d_in[13];
    const float* ffn_tm_k   = (const float*)d_in[14];
    const float* ffn_tm_r   = (const float*)d_in[15];
    const float* Wk_ff      = (const float*)d_in[16];
    const float* Wv_ff      = (const float*)d_in[17];
    const float* Wr_ff      = (const float*)d_in[18];
    float* out = (float*)d_out;

    float *x, *kx, *vx, *rx, *k, *v, *r, *wkv, *kkb;
    __nv_bfloat16 *Ah, *Al, *Bh, *Bl;
    cudaGetSymbolAddress((void**)&x,   g_x);
    cudaGetSymbolAddress((void**)&kx,  g_kx);
    cudaGetSymbolAddress((void**)&vx,  g_vx);
    cudaGetSymbolAddress((void**)&rx,  g_rx);
    cudaGetSymbolAddress((void**)&k,   g_k);
    cudaGetSymbolAddress((void**)&v,   g_v);
    cudaGetSymbolAddress((void**)&r,   g_r);
    cudaGetSymbolAddress((void**)&wkv, g_wkv);
    cudaGetSymbolAddress((void**)&kkb, g_kk);
    cudaGetSymbolAddress((void**)&Ah,  g_Ah);
    cudaGetSymbolAddress((void**)&Al,  g_Al);
    cudaGetSymbolAddress((void**)&Bh,  g_Bh);
    cudaGetSymbolAddress((void**)&Bl,  g_Bl);

    static const int SMEM_BYTES = 65536 + 1024;
    cudaFuncSetAttribute(mma_gemm<0>, cudaFuncAttributeMaxDynamicSharedMemorySize, SMEM_BYTES);
    cudaFuncSetAttribute(mma_gemm<1>, cudaFuncAttributeMaxDynamicSharedMemorySize, SMEM_BYTES);
    cudaFuncSetAttribute(mma_gemm<2>, cudaFuncAttributeMaxDynamicSharedMemorySize, SMEM_BYTES);
    cudaFuncSetAttribute(mma_gemm<3>, cudaFuncAttributeMaxDynamicSharedMemorySize, SMEM_BYTES);

    const int ebH = (T_SEQ * H_DIM) / 256;
    const int ebI = (int)(((size_t)T_SEQ * I_DIM) / 256);
    const dim3 gHH(H_DIM / 128, T_SEQ / 128);        // GEMM grid, N=2048
    const dim3 gHI(I_DIM / 128, T_SEQ / 128);        // GEMM grid, N=8192
    const dim3 wtHH(H_DIM / 32, H_DIM / 32);
    const dim3 wtHI(I_DIM / 32, H_DIM / 32);
    const dim3 wtIH(H_DIM / 32, I_DIM / 32);

    // ---- time-mix ----
    ln_kernel<<<T_SEQ, 256>>>(hidden, ln1_scale, ln1_bias, x);
    mix3_kernel<<<ebH, 256>>>(x, tm_k, tm_v, tm_r, kx, vx, rx);

    convert_act<<<ebH, 256>>>(rx, Ah, Al);
    convert_wt<<<wtHH, 256>>>(Wr, Bh, Bl, H_DIM, H_DIM);
    mma_gemm<1><<<gHH, 256, SMEM_BYTES>>>(Ah, Al, Bh, Bl, r, nullptr, T_SEQ, H_DIM, H_DIM);

    convert_act<<<ebH, 256>>>(kx, Ah, Al);
    convert_wt<<<wtHH, 256>>>(Wk, Bh, Bl, H_DIM, H_DIM);
    mma_gemm<0><<<gHH, 256, SMEM_BYTES>>>(Ah, Al, Bh, Bl, k, nullptr, T_SEQ, H_DIM, H_DIM);

    convert_act<<<ebH, 256>>>(vx, Ah, Al);
    convert_wt<<<wtHH, 256>>>(Wv, Bh, Bl, H_DIM, H_DIM);
    mma_gemm<0><<<gHH, 256, SMEM_BYTES>>>(Ah, Al, Bh, Bl, v, nullptr, T_SEQ, H_DIM, H_DIM);

    wkv_kernel<<<H_DIM / 256, 256>>>(k, v, r, time_first, time_decay, wkv);

    convert_act<<<ebH, 256>>>(wkv, Ah, Al);
    convert_wt<<<wtHH, 256>>>(Wo, Bh, Bl, H_DIM, H_DIM);
    mma_gemm<3><<<gHH, 256, SMEM_BYTES>>>(Ah, Al, Bh, Bl, out, hidden, T_SEQ, H_DIM, H_DIM);

    // ---- channel-mix ----
    ln_kernel<<<T_SEQ, 256>>>(out, ln2_scale, ln2_bias, x);
    mix2_kernel<<<ebH, 256>>>(x, ffn_tm_k, ffn_tm_r, kx, rx);

    convert_act<<<ebH, 256>>>(rx, Ah, Al);
    convert_wt<<<wtHH, 256>>>(Wr_ff, Bh, Bl, H_DIM, H_DIM);
    mma_gemm<1><<<gHH, 256, SMEM_BYTES>>>(Ah, Al, Bh, Bl, r, nullptr, T_SEQ, H_DIM, H_DIM);

    convert_act<<<ebH, 256>>>(kx, Ah, Al);
    convert_wt<<<wtHI, 256>>>(Wk_ff, Bh, Bl, H_DIM, I_DIM);
    mma_gemm<2><<<gHI, 256, SMEM_BYTES>>>(Ah, Al, Bh, Bl, kkb, nullptr, T_SEQ, I_DIM, H_DIM);

    convert_act<<<ebI, 256>>>(kkb, Ah, Al);
    convert_wt<<<wtIH, 256>>>(Wv_ff, Bh, Bl, I_DIM, H_DIM);
    mma_gemm<0><<<gHH, 256, SMEM_BYTES>>>(Ah, Al, Bh, Bl, v, nullptr, T_SEQ, H_DIM, I_DIM);

    gate_add_kernel<<<ebH, 256>>>(out, r, v);
}

// round 9
// speedup vs baseline: 2.2511x; 1.2047x over previous
#include <cuda_runtime.h>
#include <cuda_bf16.h>
#include <math_constants.h>
#include <cstdint>

#define T_SEQ 4096
#define H_DIM 2048
#define I_DIM 8192

// ---------------- scratch (device globals; no runtime allocation) ----------------
__device__ float g_x  [T_SEQ * H_DIM];       // LN output
__device__ float g_k  [T_SEQ * H_DIM];
__device__ float g_v  [T_SEQ * H_DIM];       // v, later kv
__device__ float g_r  [T_SEQ * H_DIM];       // sigmoid(r), later rr
// bf16 split activation buffers
__device__ __nv_bfloat16 g_Ah[(size_t)T_SEQ * H_DIM];  // kx / wkv / ffn-kx
__device__ __nv_bfloat16 g_Al[(size_t)T_SEQ * H_DIM];
__device__ __nv_bfloat16 g_Vh[(size_t)T_SEQ * H_DIM];  // vx
__device__ __nv_bfloat16 g_Vl[(size_t)T_SEQ * H_DIM];
__device__ __nv_bfloat16 g_Rh[(size_t)T_SEQ * H_DIM];  // rx / ffn-rx
__device__ __nv_bfloat16 g_Rl[(size_t)T_SEQ * H_DIM];
__device__ __nv_bfloat16 g_Kh[(size_t)T_SEQ * I_DIM];  // kk split (ffn inner)
__device__ __nv_bfloat16 g_Kl[(size_t)T_SEQ * I_DIM];
// weight split buffers (transposed, K-major)
__device__ __nv_bfloat16 g_Bh[(size_t)H_DIM * I_DIM];
__device__ __nv_bfloat16 g_Bl[(size_t)H_DIM * I_DIM];

// ---------------- helpers ----------------
__device__ __forceinline__ uint32_t smem_u32(const void* p) {
    uint32_t a;
    asm("{ .reg .u64 t; cvta.to.shared.u64 t, %1; cvt.u32.u64 %0, t; }" : "=r"(a) : "l"(p));
    return a;
}
#define SWZ128(o) ((o) ^ (((o) >> 3) & 0x70))

__device__ __forceinline__ void cp_async16(uint32_t dst, const void* src) {
    asm volatile("cp.async.cg.shared.global [%0], [%1], 16;" :: "r"(dst), "l"(src));
}
#define CP_COMMIT() asm volatile("cp.async.commit_group;" ::: "memory")

__device__ __forceinline__ void ldm_x4(uint32_t* r, uint32_t addr) {
    asm volatile("ldmatrix.sync.aligned.m8n8.x4.shared.b16 {%0,%1,%2,%3}, [%4];"
                 : "=r"(r[0]), "=r"(r[1]), "=r"(r[2]), "=r"(r[3]) : "r"(addr));
}
__device__ __forceinline__ void mma16816(float* c, const uint32_t* a, const uint32_t* b) {
    asm volatile(
        "mma.sync.aligned.m16n8k16.row.col.f32.bf16.bf16.f32 "
        "{%0,%1,%2,%3}, {%4,%5,%6,%7}, {%8,%9}, {%0,%1,%2,%3};"
        : "+f"(c[0]), "+f"(c[1]), "+f"(c[2]), "+f"(c[3])
        : "r"(a[0]), "r"(a[1]), "r"(a[2]), "r"(a[3]), "r"(b[0]), "r"(b[1]));
}
__device__ __forceinline__ void split_bf16(float v, __nv_bfloat16& h, __nv_bfloat16& l) {
    h = __float2bfloat16(v);
    l = __float2bfloat16(v - __bfloat162float(h));
}

// ---------------- mma.sync GEMM: C[M,N] = A[M,K] @ B[N,K]^T  (3-term bf16 split) -------
// BM=128, BN=128, BK=64, 256 threads; 3-stage cp.async pipeline; SW128 smem.
// EPI: 0=none 1=sigmoid 2=relu^2(fp32) 3=+=res 4=relu^2 -> bf16 hi/lo split
template <int EPI>
__global__ __launch_bounds__(256) void mma_gemm(const __nv_bfloat16* __restrict__ Ah,
                                                const __nv_bfloat16* __restrict__ Al,
                                                const __nv_bfloat16* __restrict__ Bh,
                                                const __nv_bfloat16* __restrict__ Bl,
                                                float* __restrict__ C,
                                                const float* __restrict__ res,
                                                __nv_bfloat16* __restrict__ Chi,
                                                __nv_bfloat16* __restrict__ Clo,
                                                int M, int N, int K) {
    extern __shared__ char dsm[];
    char* smem = (char*)(((uintptr_t)dsm + 1023u) & ~(uintptr_t)1023u);
    const uint32_t sbase = smem_u32(smem);

    const int tid = threadIdx.x;
    const int wid = tid >> 5, lane = tid & 31;
    const int warp_m = wid & 3;        // 4 warps along M (32 rows each)
    const int warp_n = wid >> 2;       // 2 warps along N (64 cols each)
    const int bm = blockIdx.y * 128, bn = blockIdx.x * 128;

    const int KC = K >> 6;             // 64-wide K chunks per region
    const int NC = 3 * KC;             // 3 split terms: AhBh, AlBh, AhBl

    const int lrow = tid >> 3;         // 0..31 (cp.async row)
    const int lseg = tid & 7;          // 0..7  (16B segment)

    // ldmatrix per-lane coordinates
    const int a_row = (lane & 15);
    const int a_kb  = (lane >> 4) * 16;
    const int b_row = (lane & 7) + ((lane >> 4) << 3);
    const int b_kb  = ((lane >> 3) & 1) * 16;

    float acc[2][8][4];
#pragma unroll
    for (int i = 0; i < 2; i++)
#pragma unroll
        for (int j = 0; j < 8; j++)
#pragma unroll
            for (int q = 0; q < 4; q++) acc[i][j][q] = 0.f;

    auto issue = [&](int c, int p) {
        const int region = c / KC;
        const int k0 = (c - region * KC) << 6;
        const __nv_bfloat16* Asrc = (region == 1) ? Al : Ah;
        const __nv_bfloat16* Bsrc = (region == 2) ? Bl : Bh;
        const uint32_t abuf = sbase + p * 32768;
        const uint32_t bbuf = abuf + 16384;
#pragma unroll
        for (int i = 0; i < 4; i++) {
            const int row = i * 32 + lrow;
            const uint32_t off = SWZ128((uint32_t)(row * 128 + lseg * 16));
            cp_async16(abuf + off, Asrc + (size_t)(bm + row) * K + k0 + lseg * 8);
            cp_async16(bbuf + off, Bsrc + (size_t)(bn + row) * K + k0 + lseg * 8);
        }
        CP_COMMIT();
    };

    issue(0, 0);
    issue(1, 1);

    for (int c = 0; c < NC; c++) {
        if (c + 1 < NC) {
            asm volatile("cp.async.wait_group 1;" ::: "memory");
        } else {
            asm volatile("cp.async.wait_group 0;" ::: "memory");
        }
        __syncthreads();
        if (c + 2 < NC) issue(c + 2, (c + 2) % 3);

        const uint32_t abuf = sbase + (c % 3) * 32768;
        const uint32_t bbuf = abuf + 16384;
#pragma unroll
        for (int ks = 0; ks < 4; ks++) {
            uint32_t afr[2][4];
#pragma unroll
            for (int mt = 0; mt < 2; mt++) {
                const uint32_t off = (uint32_t)((warp_m * 32 + mt * 16 + a_row) * 128 + ks * 32 + a_kb);
                ldm_x4(afr[mt], abuf + SWZ128(off));
            }
            uint32_t bfr[8][2];
#pragma unroll
            for (int np = 0; np < 4; np++) {
                uint32_t r[4];
                const uint32_t off = (uint32_t)((warp_n * 64 + np * 16 + b_row) * 128 + ks * 32 + b_kb);
                ldm_x4(r, bbuf + SWZ128(off));
                bfr[2 * np][0] = r[0];  bfr[2 * np][1] = r[1];
                bfr[2 * np + 1][0] = r[2];  bfr[2 * np + 1][1] = r[3];
            }
#pragma unroll
            for (int mt = 0; mt < 2; mt++)
#pragma unroll
                for (int nt = 0; nt < 8; nt++)
                    mma16816(acc[mt][nt], afr[mt], bfr[nt]);
        }
        __syncthreads();
    }

    // ---- epilogue ----
    const int trow = lane >> 2;
    const int tcol = (lane & 3) * 2;
#pragma unroll
    for (int mt = 0; mt < 2; mt++) {
#pragma unroll
        for (int nt = 0; nt < 8; nt++) {
            const int row0 = bm + warp_m * 32 + mt * 16 + trow;
            const int col  = bn + warp_n * 64 + nt * 8 + tcol;
#pragma unroll
            for (int h = 0; h < 2; h++) {
                const int row = row0 + h * 8;
                float v0 = acc[mt][nt][2 * h + 0];
                float v1 = acc[mt][nt][2 * h + 1];
                const size_t base = (size_t)row * N + col;
                if (EPI == 1) {
                    v0 = 1.f / (1.f + __expf(-v0));
                    v1 = 1.f / (1.f + __expf(-v1));
                } else if (EPI == 2 || EPI == 4) {
                    v0 = fmaxf(v0, 0.f); v0 *= v0;
                    v1 = fmaxf(v1, 0.f); v1 *= v1;
                } else if (EPI == 3) {
                    const float2 rv = *reinterpret_cast<const float2*>(&res[base]);
                    v0 += rv.x; v1 += rv.y;
                }
                if (EPI == 4) {
                    __nv_bfloat16 h0, l0, h1, l1;
                    split_bf16(v0, h0, l0);
                    split_bf16(v1, h1, l1);
                    *reinterpret_cast<__nv_bfloat162*>(&Chi[base]) = __nv_bfloat162(h0, h1);
                    *reinterpret_cast<__nv_bfloat162*>(&Clo[base]) = __nv_bfloat162(l0, l1);
                } else {
                    *reinterpret_cast<float2*>(&C[base]) = make_float2(v0, v1);
                }
            }
        }
    }
}

// ---------------- weight transpose + split: W[K,N] fp32 -> [N,K] bf16 hi/lo ----------------
__global__ __launch_bounds__(256) void convert_wt(const float* __restrict__ W,
                                                  __nv_bfloat16* __restrict__ Th,
                                                  __nv_bfloat16* __restrict__ Tl,
                                                  int K, int N) {
    __shared__ float tile[32][33];
    const int tx = threadIdx.x & 31, ty = threadIdx.x >> 5;
    const int k0 = blockIdx.y * 32, n0 = blockIdx.x * 32;
#pragma unroll
    for (int j = 0; j < 4; j++)
        tile[ty + j * 8][tx] = W[(size_t)(k0 + ty + j * 8) * N + n0 + tx];
    __syncthreads();
#pragma unroll
    for (int j = 0; j < 4; j++) {
        const float v = tile[tx][ty + j * 8];
        __nv_bfloat16 h, l;
        split_bf16(v, h, l);
        const size_t o = (size_t)(n0 + ty + j * 8) * K + k0 + tx;
        Th[o] = h;
        Tl[o] = l;
    }
}

// ---------------- LayerNorm ----------------
__global__ __launch_bounds__(256) void ln_kernel(const float* __restrict__ in,
                                                 const float* __restrict__ sc,
                                                 const float* __restrict__ bi,
                                                 float* __restrict__ out) {
    __shared__ float red0[8], red1[8];
    const int t = blockIdx.x;
    const float* row = in + (size_t)t * H_DIM;
    float v[8];
    float s = 0.f, ss = 0.f;
#pragma unroll
    for (int i = 0; i < 8; i++) {
        v[i] = row[threadIdx.x + i * 256];
        s += v[i]; ss += v[i] * v[i];
    }
#pragma unroll
    for (int o = 16; o; o >>= 1) {
        s  += __shfl_xor_sync(0xffffffffu, s, o);
        ss += __shfl_xor_sync(0xffffffffu, ss, o);
    }
    const int w = threadIdx.x >> 5, l = threadIdx.x & 31;
    if (l == 0) { red0[w] = s; red1[w] = ss; }
    __syncthreads();
    if (threadIdx.x < 32) {
        s  = (l < 8) ? red0[l] : 0.f;
        ss = (l < 8) ? red1[l] : 0.f;
#pragma unroll
        for (int o = 4; o; o >>= 1) {
            s  += __shfl_xor_sync(0xffffffffu, s, o);
            ss += __shfl_xor_sync(0xffffffffu, ss, o);
        }
        if (l == 0) { red0[0] = s; red1[0] = ss; }
    }
    __syncthreads();
    const float mean = red0[0] * (1.f / H_DIM);
    const float var  = red1[0] * (1.f / H_DIM) - mean * mean;
    const float inv  = rsqrtf(var + 1e-5f);
    float* orow = out + (size_t)t * H_DIM;
#pragma unroll
    for (int i = 0; i < 8; i++) {
        const int h = threadIdx.x + i * 256;
        orow[h] = (v[i] - mean) * inv * sc[h] + bi[h];
    }
}

// ---------------- token-shift mixes, fused bf16 split output ----------------
__global__ __launch_bounds__(256) void mix3_kernel(const float* __restrict__ x,
                                                   const float* __restrict__ tmk,
                                                   const float* __restrict__ tmv,
                                                   const float* __restrict__ tmr,
                                                   __nv_bfloat16* __restrict__ kxh, __nv_bfloat16* __restrict__ kxl,
                                                   __nv_bfloat16* __restrict__ vxh, __nv_bfloat16* __restrict__ vxl,
                                                   __nv_bfloat16* __restrict__ rxh, __nv_bfloat16* __restrict__ rxl) {
    const int idx = blockIdx.x * 256 + threadIdx.x;
    const int h = idx & (H_DIM - 1);
    const float xv = x[idx];
    const float cx = (idx >= H_DIM) ? x[idx - H_DIM] : 0.f;
    const float a = tmk[h], b = tmv[h], c = tmr[h];
    __nv_bfloat16 hh, ll;
    split_bf16(xv * a + cx * (1.f - a), hh, ll);  kxh[idx] = hh; kxl[idx] = ll;
    split_bf16(xv * b + cx * (1.f - b), hh, ll);  vxh[idx] = hh; vxl[idx] = ll;
    split_bf16(xv * c + cx * (1.f - c), hh, ll);  rxh[idx] = hh; rxl[idx] = ll;
}

__global__ __launch_bounds__(256) void mix2_kernel(const float* __restrict__ x,
                                                   const float* __restrict__ tmk,
                                                   const float* __restrict__ tmr,
                                                   __nv_bfloat16* __restrict__ kxh, __nv_bfloat16* __restrict__ kxl,
                                                   __nv_bfloat16* __restrict__ rxh, __nv_bfloat16* __restrict__ rxl) {
    const int idx = blockIdx.x * 256 + threadIdx.x;
    const int h = idx & (H_DIM - 1);
    const float xv = x[idx];
    const float cx = (idx >= H_DIM) ? x[idx - H_DIM] : 0.f;
    const float a = tmk[h], c = tmr[h];
    __nv_bfloat16 hh, ll;
    split_bf16(xv * a + cx * (1.f - a), hh, ll);  kxh[idx] = hh; kxl[idx] = ll;
    split_bf16(xv * c + cx * (1.f - c), hh, ll);  rxh[idx] = hh; rxl[idx] = ll;
}

// ---------------- WKV serial scan; writes r*wkv as bf16 hi/lo ----------------
__global__ __launch_bounds__(256) void wkv_kernel(const float* __restrict__ k,
                                                  const float* __restrict__ v,
                                                  const float* __restrict__ r,
                                                  const float* __restrict__ time_first,
                                                  const float* __restrict__ time_decay,
                                                  __nv_bfloat16* __restrict__ outh,
                                                  __nv_bfloat16* __restrict__ outl) {
    const int h = blockIdx.x * 256 + threadIdx.x;
    const float u = time_first[h];
    const float w = -__expf(time_decay[h]);
    float aa = 0.f, bb = 0.f, pp = -CUDART_INF_F;
    for (int t = 0; t < T_SEQ; t++) {
        const size_t idx = (size_t)t * H_DIM + h;
        const float kk = k[idx];
        const float vv = v[idx];
        const float ww = u + kk;
        const float p  = fmaxf(pp, ww);
        const float e1 = __expf(pp - p);
        const float e2 = __expf(ww - p);
        const float o  = r[idx] * (e1 * aa + e2 * vv) / (e1 * bb + e2);
        __nv_bfloat16 hh, ll;
        split_bf16(o, hh, ll);
        outh[idx] = hh; outl[idx] = ll;
        const float ww2 = w + pp;
        const float p2  = fmaxf(ww2, kk);
        const float e1b = __expf(ww2 - p2);
        const float e2b = __expf(kk - p2);
        aa = e1b * aa + e2b * vv;
        bb = e1b * bb + e2b;
        pp = p2;
    }
}

__global__ __launch_bounds__(256) void gate_add_kernel(float* __restrict__ out,
                                                       const float* __restrict__ rr,
                                                       const float* __restrict__ kv) {
    const int idx = blockIdx.x * 256 + threadIdx.x;
    out[idx] += rr[idx] * kv[idx];
}

// ---------------- launch ----------------
extern "C" void kernel_launch(void* const* d_in, const int* in_sizes, int n_in,
                              void* d_out, int out_size) {
    const float* hidden     = (const float*)d_in[0];
    const float* ln1_scale  = (const float*)d_in[1];
    const float* ln1_bias   = (const float*)d_in[2];
    const float* ln2_scale  = (const float*)d_in[3];
    const float* ln2_bias   = (const float*)d_in[4];
    const float* time_decay = (const float*)d_in[5];
    const float* time_first = (const float*)d_in[6];
    const float* tm_k       = (const float*)d_in[7];
    const float* tm_v       = (const float*)d_in[8];
    const float* tm_r       = (const float*)d_in[9];
    const float* Wk         = (const float*)d_in[10];
    const float* Wv         = (const float*)d_in[11];
    const float* Wr         = (const float*)d_in[12];
    const float* Wo         = (const float*)d_in[13];
    const float* ffn_tm_k   = (const float*)d_in[14];
    const float* ffn_tm_r   = (const float*)d_in[15];
    const float* Wk_ff      = (const float*)d_in[16];
    const float* Wv_ff      = (const float*)d_in[17];
    const float* Wr_ff      = (const float*)d_in[18];
    float* out = (float*)d_out;

    float *x, *k, *v, *r;
    __nv_bfloat16 *Ah, *Al, *Vh, *Vl, *Rh, *Rl, *Kh, *Kl, *Bh, *Bl;
    cudaGetSymbolAddress((void**)&x,  g_x);
    cudaGetSymbolAddress((void**)&k,  g_k);
    cudaGetSymbolAddress((void**)&v,  g_v);
    cudaGetSymbolAddress((void**)&r,  g_r);
    cudaGetSymbolAddress((void**)&Ah, g_Ah);
    cudaGetSymbolAddress((void**)&Al, g_Al);
    cudaGetSymbolAddress((void**)&Vh, g_Vh);
    cudaGetSymbolAddress((void**)&Vl, g_Vl);
    cudaGetSymbolAddress((void**)&Rh, g_Rh);
    cudaGetSymbolAddress((void**)&Rl, g_Rl);
    cudaGetSymbolAddress((void**)&Kh, g_Kh);
    cudaGetSymbolAddress((void**)&Kl, g_Kl);
    cudaGetSymbolAddress((void**)&Bh, g_Bh);
    cudaGetSymbolAddress((void**)&Bl, g_Bl);

    static const int SMEM_BYTES = 3 * 32768 + 1024;
    cudaFuncSetAttribute(mma_gemm<0>, cudaFuncAttributeMaxDynamicSharedMemorySize, SMEM_BYTES);
    cudaFuncSetAttribute(mma_gemm<1>, cudaFuncAttributeMaxDynamicSharedMemorySize, SMEM_BYTES);
    cudaFuncSetAttribute(mma_gemm<3>, cudaFuncAttributeMaxDynamicSharedMemorySize, SMEM_BYTES);
    cudaFuncSetAttribute(mma_gemm<4>, cudaFuncAttributeMaxDynamicSharedMemorySize, SMEM_BYTES);

    const int ebH = (T_SEQ * H_DIM) / 256;
    const dim3 gHH(H_DIM / 128, T_SEQ / 128);
    const dim3 gHI(I_DIM / 128, T_SEQ / 128);
    const dim3 wtHH(H_DIM / 32, H_DIM / 32);
    const dim3 wtHI(I_DIM / 32, H_DIM / 32);
    const dim3 wtIH(H_DIM / 32, I_DIM / 32);

    // ---- time-mix ----
    ln_kernel<<<T_SEQ, 256>>>(hidden, ln1_scale, ln1_bias, x);
    mix3_kernel<<<ebH, 256>>>(x, tm_k, tm_v, tm_r, Ah, Al, Vh, Vl, Rh, Rl);

    convert_wt<<<wtHH, 256>>>(Wr, Bh, Bl, H_DIM, H_DIM);
    mma_gemm<1><<<gHH, 256, SMEM_BYTES>>>(Rh, Rl, Bh, Bl, r, nullptr, nullptr, nullptr, T_SEQ, H_DIM, H_DIM);

    convert_wt<<<wtHH, 256>>>(Wk, Bh, Bl, H_DIM, H_DIM);
    mma_gemm<0><<<gHH, 256, SMEM_BYTES>>>(Ah, Al, Bh, Bl, k, nullptr, nullptr, nullptr, T_SEQ, H_DIM, H_DIM);

    convert_wt<<<wtHH, 256>>>(Wv, Bh, Bl, H_DIM, H_DIM);
    mma_gemm<0><<<gHH, 256, SMEM_BYTES>>>(Vh, Vl, Bh, Bl, v, nullptr, nullptr, nullptr, T_SEQ, H_DIM, H_DIM);

    wkv_kernel<<<H_DIM / 256, 256>>>(k, v, r, time_first, time_decay, Ah, Al);  // r*wkv -> Ah/Al

    convert_wt<<<wtHH, 256>>>(Wo, Bh, Bl, H_DIM, H_DIM);
    mma_gemm<3><<<gHH, 256, SMEM_BYTES>>>(Ah, Al, Bh, Bl, out, hidden, nullptr, nullptr, T_SEQ, H_DIM, H_DIM);

    // ---- channel-mix ----
    ln_kernel<<<T_SEQ, 256>>>(out, ln2_scale, ln2_bias, x);
    mix2_kernel<<<ebH, 256>>>(x, ffn_tm_k, ffn_tm_r, Ah, Al, Rh, Rl);

    convert_wt<<<wtHH, 256>>>(Wr_ff, Bh, Bl, H_DIM, H_DIM);
    mma_gemm<1><<<gHH, 256, SMEM_BYTES>>>(Rh, Rl, Bh, Bl, r, nullptr, nullptr, nullptr, T_SEQ, H_DIM, H_DIM);

    convert_wt<<<wtHI, 256>>>(Wk_ff, Bh, Bl, H_DIM, I_DIM);
    mma_gemm<4><<<gHI, 256, SMEM_BYTES>>>(Ah, Al, Bh, Bl, nullptr, nullptr, Kh, Kl, T_SEQ, I_DIM, H_DIM);

    convert_wt<<<wtIH, 256>>>(Wv_ff, Bh, Bl, I_DIM, H_DIM);
    mma_gemm<0><<<gHH, 256, SMEM_BYTES>>>(Kh, Kl, Bh, Bl, v, nullptr, nullptr, nullptr, T_SEQ, H_DIM, I_DIM);

    gate_add_kernel<<<ebH, 256>>>(out, r, v);
}

// round 10
// speedup vs baseline: 2.6614x; 1.1823x over previous
#include <cuda_runtime.h>
#include <cuda_bf16.h>
#include <math_constants.h>
#include <cstdint>

#define T_SEQ 4096
#define H_DIM 2048
#define I_DIM 8192

// ---------------- scratch (device globals; no runtime allocation) ----------------
__device__ float g_x  [T_SEQ * H_DIM];       // LN output
__device__ float g_k  [T_SEQ * H_DIM];
__device__ float g_v  [T_SEQ * H_DIM];       // v, later kv
__device__ float g_r  [T_SEQ * H_DIM];       // sigmoid(r), later rr
// bf16 split activation buffers
__device__ __nv_bfloat16 g_Ah[(size_t)T_SEQ * H_DIM];  // kx / wkv / ffn-kx
__device__ __nv_bfloat16 g_Al[(size_t)T_SEQ * H_DIM];
__device__ __nv_bfloat16 g_Vh[(size_t)T_SEQ * H_DIM];  // vx
__device__ __nv_bfloat16 g_Vl[(size_t)T_SEQ * H_DIM];
__device__ __nv_bfloat16 g_Rh[(size_t)T_SEQ * H_DIM];  // rx / ffn-rx
__device__ __nv_bfloat16 g_Rl[(size_t)T_SEQ * H_DIM];
__device__ __nv_bfloat16 g_Kh[(size_t)T_SEQ * I_DIM];  // kk split (ffn inner)
__device__ __nv_bfloat16 g_Kl[(size_t)T_SEQ * I_DIM];
// weight split buffers (transposed, K-major)
__device__ __nv_bfloat16 g_Bh[(size_t)H_DIM * I_DIM];
__device__ __nv_bfloat16 g_Bl[(size_t)H_DIM * I_DIM];

// ---------------- helpers ----------------
__device__ __forceinline__ uint32_t smem_u32(const void* p) {
    uint32_t a;
    asm("{ .reg .u64 t; cvta.to.shared.u64 t, %1; cvt.u32.u64 %0, t; }" : "=r"(a) : "l"(p));
    return a;
}
#define SWZ128(o) ((o) ^ (((o) >> 3) & 0x70))

__device__ __forceinline__ void cp_async16(uint32_t dst, const void* src) {
    asm volatile("cp.async.cg.shared.global [%0], [%1], 16;" :: "r"(dst), "l"(src));
}
#define CP_COMMIT() asm volatile("cp.async.commit_group;" ::: "memory")

__device__ __forceinline__ void ldm_x4(uint32_t* r, uint32_t addr) {
    asm volatile("ldmatrix.sync.aligned.m8n8.x4.shared.b16 {%0,%1,%2,%3}, [%4];"
                 : "=r"(r[0]), "=r"(r[1]), "=r"(r[2]), "=r"(r[3]) : "r"(addr));
}
__device__ __forceinline__ void mma16816(float* c, const uint32_t* a, const uint32_t* b) {
    asm volatile(
        "mma.sync.aligned.m16n8k16.row.col.f32.bf16.bf16.f32 "
        "{%0,%1,%2,%3}, {%4,%5,%6,%7}, {%8,%9}, {%0,%1,%2,%3};"
        : "+f"(c[0]), "+f"(c[1]), "+f"(c[2]), "+f"(c[3])
        : "r"(a[0]), "r"(a[1]), "r"(a[2]), "r"(a[3]), "r"(b[0]), "r"(b[1]));
}
__device__ __forceinline__ void split_bf16(float v, __nv_bfloat16& h, __nv_bfloat16& l) {
    h = __float2bfloat16(v);
    l = __float2bfloat16(v - __bfloat162float(h));
}

// ---------------- mma.sync GEMM: C[M,N] = A[M,K] @ B[N,K]^T  (3-term bf16 split) -------
// BM=128, BN=128, BK=64, 256 threads; 3-stage cp.async pipeline; SW128 smem.
// EPI: 0=none 1=sigmoid 2=relu^2(fp32) 3=+=res 4=relu^2 -> bf16 hi/lo split
template <int EPI>
__global__ __launch_bounds__(256) void mma_gemm(const __nv_bfloat16* __restrict__ Ah,
                                                const __nv_bfloat16* __restrict__ Al,
                                                const __nv_bfloat16* __restrict__ Bh,
                                                const __nv_bfloat16* __restrict__ Bl,
                                                float* __restrict__ C,
                                                const float* __restrict__ res,
                                                __nv_bfloat16* __restrict__ Chi,
                                                __nv_bfloat16* __restrict__ Clo,
                                                int M, int N, int K) {
    extern __shared__ char dsm[];
    char* smem = (char*)(((uintptr_t)dsm + 1023u) & ~(uintptr_t)1023u);
    const uint32_t sbase = smem_u32(smem);

    const int tid = threadIdx.x;
    const int wid = tid >> 5, lane = tid & 31;
    const int warp_m = wid & 3;        // 4 warps along M (32 rows each)
    const int warp_n = wid >> 2;       // 2 warps along N (64 cols each)
    const int bm = blockIdx.y * 128, bn = blockIdx.x * 128;

    const int KC = K >> 6;             // 64-wide K chunks per region
    const int NC = 3 * KC;             // 3 split terms: AhBh, AlBh, AhBl

    const int lrow = tid >> 3;         // 0..31 (cp.async row)
    const int lseg = tid & 7;          // 0..7  (16B segment)

    // ldmatrix per-lane coordinates
    const int a_row = (lane & 15);
    const int a_kb  = (lane >> 4) * 16;
    const int b_row = (lane & 7) + ((lane >> 4) << 3);
    const int b_kb  = ((lane >> 3) & 1) * 16;

    float acc[2][8][4];
#pragma unroll
    for (int i = 0; i < 2; i++)
#pragma unroll
        for (int j = 0; j < 8; j++)
#pragma unroll
            for (int q = 0; q < 4; q++) acc[i][j][q] = 0.f;

    auto issue = [&](int c, int p) {
        const int region = c / KC;
        const int k0 = (c - region * KC) << 6;
        const __nv_bfloat16* Asrc = (region == 1) ? Al : Ah;
        const __nv_bfloat16* Bsrc = (region == 2) ? Bl : Bh;
        const uint32_t abuf = sbase + p * 32768;
        const uint32_t bbuf = abuf + 16384;
#pragma unroll
        for (int i = 0; i < 4; i++) {
            const int row = i * 32 + lrow;
            const uint32_t off = SWZ128((uint32_t)(row * 128 + lseg * 16));
            cp_async16(abuf + off, Asrc + (size_t)(bm + row) * K + k0 + lseg * 8);
            cp_async16(bbuf + off, Bsrc + (size_t)(bn + row) * K + k0 + lseg * 8);
        }
        CP_COMMIT();
    };

    issue(0, 0);
    issue(1, 1);

    for (int c = 0; c < NC; c++) {
        if (c + 1 < NC) {
            asm volatile("cp.async.wait_group 1;" ::: "memory");
        } else {
            asm volatile("cp.async.wait_group 0;" ::: "memory");
        }
        __syncthreads();
        if (c + 2 < NC) issue(c + 2, (c + 2) % 3);

        const uint32_t abuf = sbase + (c % 3) * 32768;
        const uint32_t bbuf = abuf + 16384;
#pragma unroll
        for (int ks = 0; ks < 4; ks++) {
            uint32_t afr[2][4];
#pragma unroll
            for (int mt = 0; mt < 2; mt++) {
                const uint32_t off = (uint32_t)((warp_m * 32 + mt * 16 + a_row) * 128 + ks * 32 + a_kb);
                ldm_x4(afr[mt], abuf + SWZ128(off));
            }
            uint32_t bfr[8][2];
#pragma unroll
            for (int np = 0; np < 4; np++) {
                uint32_t r[4];
                const uint32_t off = (uint32_t)((warp_n * 64 + np * 16 + b_row) * 128 + ks * 32 + b_kb);
                ldm_x4(r, bbuf + SWZ128(off));
                bfr[2 * np][0] = r[0];  bfr[2 * np][1] = r[1];
                bfr[2 * np + 1][0] = r[2];  bfr[2 * np + 1][1] = r[3];
            }
#pragma unroll
            for (int mt = 0; mt < 2; mt++)
#pragma unroll
                for (int nt = 0; nt < 8; nt++)
                    mma16816(acc[mt][nt], afr[mt], bfr[nt]);
        }
        __syncthreads();
    }

    // ---- epilogue ----
    const int trow = lane >> 2;
    const int tcol = (lane & 3) * 2;
#pragma unroll
    for (int mt = 0; mt < 2; mt++) {
#pragma unroll
        for (int nt = 0; nt < 8; nt++) {
            const int row0 = bm + warp_m * 32 + mt * 16 + trow;
            const int col  = bn + warp_n * 64 + nt * 8 + tcol;
#pragma unroll
            for (int h = 0; h < 2; h++) {
                const int row = row0 + h * 8;
                float v0 = acc[mt][nt][2 * h + 0];
                float v1 = acc[mt][nt][2 * h + 1];
                const size_t base = (size_t)row * N + col;
                if (EPI == 1) {
                    v0 = 1.f / (1.f + __expf(-v0));
                    v1 = 1.f / (1.f + __expf(-v1));
                } else if (EPI == 2 || EPI == 4) {
                    v0 = fmaxf(v0, 0.f); v0 *= v0;
                    v1 = fmaxf(v1, 0.f); v1 *= v1;
                } else if (EPI == 3) {
                    const float2 rv = *reinterpret_cast<const float2*>(&res[base]);
                    v0 += rv.x; v1 += rv.y;
                }
                if (EPI == 4) {
                    __nv_bfloat16 h0, l0, h1, l1;
                    split_bf16(v0, h0, l0);
                    split_bf16(v1, h1, l1);
                    *reinterpret_cast<__nv_bfloat162*>(&Chi[base]) = __nv_bfloat162(h0, h1);
                    *reinterpret_cast<__nv_bfloat162*>(&Clo[base]) = __nv_bfloat162(l0, l1);
                } else {
                    *reinterpret_cast<float2*>(&C[base]) = make_float2(v0, v1);
                }
            }
        }
    }
}

// ---------------- weight transpose + split: W[K,N] fp32 -> [N,K] bf16 hi/lo ----------------
__global__ __launch_bounds__(256) void convert_wt(const float* __restrict__ W,
                                                  __nv_bfloat16* __restrict__ Th,
                                                  __nv_bfloat16* __restrict__ Tl,
                                                  int K, int N) {
    __shared__ float tile[32][33];
    const int tx = threadIdx.x & 31, ty = threadIdx.x >> 5;
    const int k0 = blockIdx.y * 32, n0 = blockIdx.x * 32;
#pragma unroll
    for (int j = 0; j < 4; j++)
        tile[ty + j * 8][tx] = W[(size_t)(k0 + ty + j * 8) * N + n0 + tx];
    __syncthreads();
#pragma unroll
    for (int j = 0; j < 4; j++) {
        const float v = tile[tx][ty + j * 8];
        __nv_bfloat16 h, l;
        split_bf16(v, h, l);
        const size_t o = (size_t)(n0 + ty + j * 8) * K + k0 + tx;
        Th[o] = h;
        Tl[o] = l;
    }
}

// ---------------- LayerNorm ----------------
__global__ __launch_bounds__(256) void ln_kernel(const float* __restrict__ in,
                                                 const float* __restrict__ sc,
                                                 const float* __restrict__ bi,
                                                 float* __restrict__ out) {
    __shared__ float red0[8], red1[8];
    const int t = blockIdx.x;
    const float* row = in + (size_t)t * H_DIM;
    float v[8];
    float s = 0.f, ss = 0.f;
#pragma unroll
    for (int i = 0; i < 8; i++) {
        v[i] = row[threadIdx.x + i * 256];
        s += v[i]; ss += v[i] * v[i];
    }
#pragma unroll
    for (int o = 16; o; o >>= 1) {
        s  += __shfl_xor_sync(0xffffffffu, s, o);
        ss += __shfl_xor_sync(0xffffffffu, ss, o);
    }
    const int w = threadIdx.x >> 5, l = threadIdx.x & 31;
    if (l == 0) { red0[w] = s; red1[w] = ss; }
    __syncthreads();
    if (threadIdx.x < 32) {
        s  = (l < 8) ? red0[l] : 0.f;
        ss = (l < 8) ? red1[l] : 0.f;
#pragma unroll
        for (int o = 4; o; o >>= 1) {
            s  += __shfl_xor_sync(0xffffffffu, s, o);
            ss += __shfl_xor_sync(0xffffffffu, ss, o);
        }
        if (l == 0) { red0[0] = s; red1[0] = ss; }
    }
    __syncthreads();
    const float mean = red0[0] * (1.f / H_DIM);
    const float var  = red1[0] * (1.f / H_DIM) - mean * mean;
    const float inv  = rsqrtf(var + 1e-5f);
    float* orow = out + (size_t)t * H_DIM;
#pragma unroll
    for (int i = 0; i < 8; i++) {
        const int h = threadIdx.x + i * 256;
        orow[h] = (v[i] - mean) * inv * sc[h] + bi[h];
    }
}

// ---------------- token-shift mixes, fused bf16 split output ----------------
__global__ __launch_bounds__(256) void mix3_kernel(const float* __restrict__ x,
                                                   const float* __restrict__ tmk,
                                                   const float* __restrict__ tmv,
                                                   const float* __restrict__ tmr,
                                                   __nv_bfloat16* __restrict__ kxh, __nv_bfloat16* __restrict__ kxl,
                                                   __nv_bfloat16* __restrict__ vxh, __nv_bfloat16* __restrict__ vxl,
                                                   __nv_bfloat16* __restrict__ rxh, __nv_bfloat16* __restrict__ rxl) {
    const int idx = blockIdx.x * 256 + threadIdx.x;
    const int h = idx & (H_DIM - 1);
    const float xv = x[idx];
    const float cx = (idx >= H_DIM) ? x[idx - H_DIM] : 0.f;
    const float a = tmk[h], b = tmv[h], c = tmr[h];
    __nv_bfloat16 hh, ll;
    split_bf16(xv * a + cx * (1.f - a), hh, ll);  kxh[idx] = hh; kxl[idx] = ll;
    split_bf16(xv * b + cx * (1.f - b), hh, ll);  vxh[idx] = hh; vxl[idx] = ll;
    split_bf16(xv * c + cx * (1.f - c), hh, ll);  rxh[idx] = hh; rxl[idx] = ll;
}

__global__ __launch_bounds__(256) void mix2_kernel(const float* __restrict__ x,
                                                   const float* __restrict__ tmk,
                                                   const float* __restrict__ tmr,
                                                   __nv_bfloat16* __restrict__ kxh, __nv_bfloat16* __restrict__ kxl,
                                                   __nv_bfloat16* __restrict__ rxh, __nv_bfloat16* __restrict__ rxl) {
    const int idx = blockIdx.x * 256 + threadIdx.x;
    const int h = idx & (H_DIM - 1);
    const float xv = x[idx];
    const float cx = (idx >= H_DIM) ? x[idx - H_DIM] : 0.f;
    const float a = tmk[h], c = tmr[h];
    __nv_bfloat16 hh, ll;
    split_bf16(xv * a + cx * (1.f - a), hh, ll);  kxh[idx] = hh; kxl[idx] = ll;
    split_bf16(xv * c + cx * (1.f - c), hh, ll);  rxh[idx] = hh; rxl[idx] = ll;
}

// ---------------- WKV serial scan with group-of-16 register prefetch ----------------
// One thread per channel. Loads for a 16-step group are issued up-front (MLP ~48),
// so L2/DRAM latency is exposed once per 16 steps instead of every step.
#define WKV_G 16
__global__ __launch_bounds__(256) void wkv_kernel(const float* __restrict__ k,
                                                  const float* __restrict__ v,
                                                  const float* __restrict__ r,
                                                  const float* __restrict__ time_first,
                                                  const float* __restrict__ time_decay,
                                                  __nv_bfloat16* __restrict__ outh,
                                                  __nv_bfloat16* __restrict__ outl) {
    const int h = blockIdx.x * 256 + threadIdx.x;
    const float u = time_first[h];
    const float w = -__expf(time_decay[h]);
    float aa = 0.f, bb = 0.f, pp = -CUDART_INF_F;

    float kb[WKV_G], vb[WKV_G], rb[WKV_G];
    for (int t0 = 0; t0 < T_SEQ; t0 += WKV_G) {
        // prefetch the whole group (independent loads, coalesced across threads)
        const size_t base0 = (size_t)t0 * H_DIM + h;
#pragma unroll
        for (int j = 0; j < WKV_G; j++) {
            const size_t idx = base0 + (size_t)j * H_DIM;
            kb[j] = __ldg(&k[idx]);
            vb[j] = __ldg(&v[idx]);
            rb[j] = __ldg(&r[idx]);
        }
        // 16 serial chain steps from registers
#pragma unroll
        for (int j = 0; j < WKV_G; j++) {
            const float kk = kb[j];
            const float vv = vb[j];
            const float ww = u + kk;
            const float p  = fmaxf(pp, ww);
            const float e1 = __expf(pp - p);
            const float e2 = __expf(ww - p);
            const float o  = rb[j] * __fdividef(e1 * aa + e2 * vv, e1 * bb + e2);
            __nv_bfloat16 hh, ll;
            split_bf16(o, hh, ll);
            const size_t idx = base0 + (size_t)j * H_DIM;
            outh[idx] = hh; outl[idx] = ll;
            const float ww2 = w + pp;
            const float p2  = fmaxf(ww2, kk);
            const float e1b = __expf(ww2 - p2);
            const float e2b = __expf(kk - p2);
            aa = e1b * aa + e2b * vv;
            bb = e1b * bb + e2b;
            pp = p2;
        }
    }
}

__global__ __launch_bounds__(256) void gate_add_kernel(float* __restrict__ out,
                                                       const float* __restrict__ rr,
                                                       const float* __restrict__ kv) {
    const int idx = blockIdx.x * 256 + threadIdx.x;
    out[idx] += rr[idx] * kv[idx];
}

// ---------------- launch ----------------
extern "C" void kernel_launch(void* const* d_in, const int* in_sizes, int n_in,
                              void* d_out, int out_size) {
    const float* hidden     = (const float*)d_in[0];
    const float* ln1_scale  = (const float*)d_in[1];
    const float* ln1_bias   = (const float*)d_in[2];
    const float* ln2_scale  = (const float*)d_in[3];
    const float* ln2_bias   = (const float*)d_in[4];
    const float* time_decay = (const float*)d_in[5];
    const float* time_first = (const float*)d_in[6];
    const float* tm_k       = (const float*)d_in[7];
    const float* tm_v       = (const float*)d_in[8];
    const float* tm_r       = (const float*)d_in[9];
    const float* Wk         = (const float*)d_in[10];
    const float* Wv         = (const float*)d_in[11];
    const float* Wr         = (const float*)d_in[12];
    const float* Wo         = (const float*)d_in[13];
    const float* ffn_tm_k   = (const float*)d_in[14];
    const float* ffn_tm_r   = (const float*)d_in[15];
    const float* Wk_ff      = (const float*)d_in[16];
    const float* Wv_ff      = (const float*)d_in[17];
    const float* Wr_ff      = (const float*)d_in[18];
    float* out = (float*)d_out;

    float *x, *k, *v, *r;
    __nv_bfloat16 *Ah, *Al, *Vh, *Vl, *Rh, *Rl, *Kh, *Kl, *Bh, *Bl;
    cudaGetSymbolAddress((void**)&x,  g_x);
    cudaGetSymbolAddress((void**)&k,  g_k);
    cudaGetSymbolAddress((void**)&v,  g_v);
    cudaGetSymbolAddress((void**)&r,  g_r);
    cudaGetSymbolAddress((void**)&Ah, g_Ah);
    cudaGetSymbolAddress((void**)&Al, g_Al);
    cudaGetSymbolAddress((void**)&Vh, g_Vh);
    cudaGetSymbolAddress((void**)&Vl, g_Vl);
    cudaGetSymbolAddress((void**)&Rh, g_Rh);
    cudaGetSymbolAddress((void**)&Rl, g_Rl);
    cudaGetSymbolAddress((void**)&Kh, g_Kh);
    cudaGetSymbolAddress((void**)&Kl, g_Kl);
    cudaGetSymbolAddress((void**)&Bh, g_Bh);
    cudaGetSymbolAddress((void**)&Bl, g_Bl);

    static const int SMEM_BYTES = 3 * 32768 + 1024;
    cudaFuncSetAttribute(mma_gemm<0>, cudaFuncAttributeMaxDynamicSharedMemorySize, SMEM_BYTES);
    cudaFuncSetAttribute(mma_gemm<1>, cudaFuncAttributeMaxDynamicSharedMemorySize, SMEM_BYTES);
    cudaFuncSetAttribute(mma_gemm<3>, cudaFuncAttributeMaxDynamicSharedMemorySize, SMEM_BYTES);
    cudaFuncSetAttribute(mma_gemm<4>, cudaFuncAttributeMaxDynamicSharedMemorySize, SMEM_BYTES);

    const int ebH = (T_SEQ * H_DIM) / 256;
    const dim3 gHH(H_DIM / 128, T_SEQ / 128);
    const dim3 gHI(I_DIM / 128, T_SEQ / 128);
    const dim3 wtHH(H_DIM / 32, H_DIM / 32);
    const dim3 wtHI(I_DIM / 32, H_DIM / 32);
    const dim3 wtIH(H_DIM / 32, I_DIM / 32);

    // ---- time-mix ----
    ln_kernel<<<T_SEQ, 256>>>(hidden, ln1_scale, ln1_bias, x);
    mix3_kernel<<<ebH, 256>>>(x, tm_k, tm_v, tm_r, Ah, Al, Vh, Vl, Rh, Rl);

    convert_wt<<<wtHH, 256>>>(Wr, Bh, Bl, H_DIM, H_DIM);
    mma_gemm<1><<<gHH, 256, SMEM_BYTES>>>(Rh, Rl, Bh, Bl, r, nullptr, nullptr, nullptr, T_SEQ, H_DIM, H_DIM);

    convert_wt<<<wtHH, 256>>>(Wk, Bh, Bl, H_DIM, H_DIM);
    mma_gemm<0><<<gHH, 256, SMEM_BYTES>>>(Ah, Al, Bh, Bl, k, nullptr, nullptr, nullptr, T_SEQ, H_DIM, H_DIM);

    convert_wt<<<wtHH, 256>>>(Wv, Bh, Bl, H_DIM, H_DIM);
    mma_gemm<0><<<gHH, 256, SMEM_BYTES>>>(Vh, Vl, Bh, Bl, v, nullptr, nullptr, nullptr, T_SEQ, H_DIM, H_DIM);

    wkv_kernel<<<H_DIM / 256, 256>>>(k, v, r, time_first, time_decay, Ah, Al);  // r*wkv -> Ah/Al

    convert_wt<<<wtHH, 256>>>(Wo, Bh, Bl, H_DIM, H_DIM);
    mma_gemm<3><<<gHH, 256, SMEM_BYTES>>>(Ah, Al, Bh, Bl, out, hidden, nullptr, nullptr, T_SEQ, H_DIM, H_DIM);

    // ---- channel-mix ----
    ln_kernel<<<T_SEQ, 256>>>(out, ln2_scale, ln2_bias, x);
    mix2_kernel<<<ebH, 256>>>(x, ffn_tm_k, ffn_tm_r, Ah, Al, Rh, Rl);

    convert_wt<<<wtHH, 256>>>(Wr_ff, Bh, Bl, H_DIM, H_DIM);
    mma_gemm<1><<<gHH, 256, SMEM_BYTES>>>(Rh, Rl, Bh, Bl, r, nullptr, nullptr, nullptr, T_SEQ, H_DIM, H_DIM);

    convert_wt<<<wtHI, 256>>>(Wk_ff, Bh, Bl, H_DIM, I_DIM);
    mma_gemm<4><<<gHI, 256, SMEM_BYTES>>>(Ah, Al, Bh, Bl, nullptr, nullptr, Kh, Kl, T_SEQ, I_DIM, H_DIM);

    convert_wt<<<wtIH, 256>>>(Wv_ff, Bh, Bl, I_DIM, H_DIM);
    mma_gemm<0><<<gHH, 256, SMEM_BYTES>>>(Kh, Kl, Bh, Bl, v, nullptr, nullptr, nullptr, T_SEQ, H_DIM, I_DIM);

    gate_add_kernel<<<ebH, 256>>>(out, r, v);
}